// round 9
// baseline (speedup 1.0000x reference)
#include <cuda_runtime.h>
#include <math.h>
#include <stdint.h>

#define CONTF 13
#define CATEF 26
#define NF    39
#define ED    40
#define NA    8
#define TPB   256
#define NW    8       // warps per block; each warp owns 2 tiles of the 15
#define PAD   44      // 176B row stride: 16B-aligned, conflict-free LDS.128
#define XROWS 40      // 39 real rows + 1 zero pad row
#define XSZ   (XROWS*PAD)
#define VOCAB 100000
#define NBLK  444     // 3 persistent blocks per SM

typedef unsigned long long u64;

__device__ __forceinline__ u64 mul2(u64 a, u64 b) {
    u64 d; asm("mul.rn.f32x2 %0, %1, %2;" : "=l"(d) : "l"(a), "l"(b)); return d;
}
__device__ __forceinline__ u64 fma2(u64 a, u64 b, u64 c) {
    u64 d; asm("fma.rn.f32x2 %0, %1, %2, %3;" : "=l"(d) : "l"(a), "l"(b), "l"(c)); return d;
}
__device__ __forceinline__ u64 pk2(float lo, float hi) {
    u64 d; asm("mov.b64 %0, {%1, %2};" : "=l"(d) : "f"(lo), "f"(hi)); return d;
}
__device__ __forceinline__ void unpack2(u64 v, float& lo, float& hi) {
    asm("mov.b64 {%0, %1}, %2;" : "=f"(lo), "=f"(hi) : "l"(v));
}
__device__ __forceinline__ float sum2(u64 v) {
    float lo, hi; unpack2(v, lo, hi); return lo + hi;
}
__device__ __forceinline__ void cp16(uint32_t dst, const void* src) {
    asm volatile("cp.async.ca.shared.global [%0], [%1], 16;" :: "r"(dst), "l"(src));
}
__device__ __forceinline__ void cp4(uint32_t dst, const void* src) {
    asm volatile("cp.async.ca.shared.global [%0], [%1], 4;" :: "r"(dst), "l"(src));
}

// tile index (0..14) -> (bi, bj) of the 5x5 upper-tri block grid
__device__ __forceinline__ void tile_ij(int tt, int& bi, int& bj) {
    int b = 0, rem = tt;
    while (rem >= 5 - b) { rem -= 5 - b; b++; }
    bi = b; bj = b + rem;
}

__global__ __launch_bounds__(TPB, 3) void afm_main(
    const float* __restrict__ conts,
    const void*  __restrict__ cates_raw,
    const float* __restrict__ emb,
    const float* __restrict__ attn_W,   // (8, 40)
    const float* __restrict__ attn_b,   // (8,)
    const float* __restrict__ proj_W,   // (1, 8)
    const float* __restrict__ fc_W,     // (1, 40)
    const float* __restrict__ fc_b,     // (1,)
    float* __restrict__ out,            // (B, 1)
    int batch)
{
    __shared__ __align__(16) float xs[2][XSZ];       // double-buffered x tiles
    __shared__ __align__(16) ulonglong2 Wq[ED * 2];  // per d: 4 u64 of (W[2k][d],W[2k+1][d])
    __shared__ __align__(16) ulonglong2 fp2[10];     // fc_W d-packed, 4 dims/entry
    __shared__ float sbase[CONTF * ED];              // emb rows 0..12
    __shared__ float sconts[2][CONTF];
    __shared__ float pwb[2 * NA];                    // attn_b | proj_W
    __shared__ float sredm[NW], sreds[NW], sredq[NW];
    __shared__ int   sflag;

    const int t    = threadIdx.x;
    const int lane = t & 31;
    const int wid  = t >> 5;

    // --- int64-vs-int32 probe ---
    if (wid == 0) {
        const unsigned int* raw = (const unsigned int*)cates_raw;
        unsigned int lo = raw[2 * lane], hi = raw[2 * lane + 1];
        int ok = (hi == 0u && lo < (unsigned)VOCAB);
        unsigned int bal = __ballot_sync(0xffffffffu, ok);
        if (lane == 0) sflag = (bal == 0xffffffffu);
    }

    // --- block-lifetime parameter setup ---
    for (int e = t; e < ED * 4; e += TPB) {
        int d = e >> 2, k = e & 3;
        ((u64*)Wq)[e] = pk2(attn_W[(2 * k) * ED + d], attn_W[(2 * k + 1) * ED + d]);
    }
    if (t < 10) {
        ulonglong2 v;
        v.x = pk2(fc_W[4 * t], fc_W[4 * t + 1]);
        v.y = pk2(fc_W[4 * t + 2], fc_W[4 * t + 3]);
        fp2[t] = v;
    }
    if (t < NA) { pwb[t] = attn_b[t]; pwb[NA + t] = proj_W[t]; }
    for (int e = t; e < CONTF * ED; e += TPB) sbase[e] = emb[e];
    if (t < 2 * PAD) {                                 // zero pad row 39
        int buf = t / PAD, d = t - buf * PAD;
        xs[buf][39 * PAD + d] = 0.f;
    }
    __syncthreads();

    const int is64 = sflag;
    const long long* c64 = (const long long*)cates_raw;
    const int*       c32 = (const int*)cates_raw;
    const float fcb = fc_b[0];

    const uint32_t xs_a = (uint32_t)__cvta_generic_to_shared(&xs[0][0]);
    const uint32_t sc_a = (uint32_t)__cvta_generic_to_shared(&sconts[0][0]);

    // --- warp -> 2 tiles; lane -> (2 rows, 1 col) per tile ---
    const int tA = 2 * wid;
    const bool enB = (2 * wid + 1 < 15);
    const int tB = enB ? (2 * wid + 1) : 14;
    int biA, bjA, biB, bjB;
    tile_ij(tA, biA, bjA);
    tile_ij(tB, biB, bjB);
    const int ii = lane >> 3, jj = lane & 7;
    const int iA0 = biA * 8 + ii, iA1 = iA0 + 4, jA = bjA * 8 + jj;
    const int iB0 = biB * 8 + ii, iB1 = iB0 + 4, jB = bjB * 8 + jj;
    const bool vA0 = (iA0 < jA) && (jA < NF);
    const bool vA1 = (iA1 < jA) && (jA < NF);
    const bool vB0 = enB && (iB0 < jB) && (jB < NF);
    const bool vB1 = enB && (iB1 < jB) && (jB < NF);
    const int orA0 = iA0 * PAD, orA1 = iA1 * PAD, ocA = jA * PAD;
    const int orB0 = iB0 * PAD, orB1 = iB1 * PAD, ocB = jB * PAD;

    // --- prefetch: 26 rows x 10 x 16B segs (260 tasks) + 13 conts ---
    #define PREFETCH(b_, buf_) do {                                           \
        for (int k_ = t; k_ < 260; k_ += TPB) {                               \
            int f_ = k_ / 10, seg_ = k_ - f_ * 10;                            \
            long long idx_ = is64 ? c64[(long long)(b_) * CATEF + f_]         \
                                  : (long long)c32[(b_) * CATEF + f_];        \
            cp16(xs_a + ((buf_) * XSZ + (CONTF + f_) * PAD + seg_ * 4) * 4,   \
                 emb + idx_ * ED + seg_ * 4);                                 \
        }                                                                     \
        if (t < CONTF)                                                        \
            cp4(sc_a + ((buf_) * CONTF + t) * 4, conts + (b_) * CONTF + t);   \
        asm volatile("cp.async.commit_group;" ::: "memory");                  \
    } while (0)

    const int s0 = blockIdx.x;
    int parity = 0;
    if (s0 < batch) PREFETCH(s0, 0);

    for (int s = s0; s < batch; s += NBLK) {
        float* xb = &xs[parity][0];

        asm volatile("cp.async.wait_group 0;" ::: "memory");
        __syncthreads();

        if (s + NBLK < batch) PREFETCH(s + NBLK, parity ^ 1);

        // continuous-field rows: sbase * conts[s]
        for (int e = t; e < CONTF * ED; e += TPB) {
            int r = e / ED, d = e - r * ED;
            xb[r * PAD + d] = sbase[e] * sconts[parity][r];
        }
        __syncthreads();

        // a-packed accumulators: acc[k] = (h[2k], h[2k+1]) per slot
        u64 aA0[4], aA1[4], aB0[4], aB1[4];
        #pragma unroll
        for (int k = 0; k < 4; k++) { aA0[k] = 0ull; aA1[k] = 0ull; aB0[k] = 0ull; aB1[k] = 0ull; }
        u64 qA0 = 0ull, qA1 = 0ull, qB0 = 0ull, qB1 = 0ull;

        #pragma unroll
        for (int dv = 0; dv < 10; dv++) {            // 4 dims per iter
            ulonglong2 rA0 = *(const ulonglong2*)(xb + orA0 + dv * 4);
            ulonglong2 rA1 = *(const ulonglong2*)(xb + orA1 + dv * 4);
            ulonglong2 cA  = *(const ulonglong2*)(xb + ocA  + dv * 4);
            ulonglong2 rB0 = *(const ulonglong2*)(xb + orB0 + dv * 4);
            ulonglong2 rB1 = *(const ulonglong2*)(xb + orB1 + dv * 4);
            ulonglong2 cB  = *(const ulonglong2*)(xb + ocB  + dv * 4);

            u64 eA0a = mul2(rA0.x, cA.x), eA0b = mul2(rA0.y, cA.y);
            u64 eA1a = mul2(rA1.x, cA.x), eA1b = mul2(rA1.y, cA.y);
            u64 eB0a = mul2(rB0.x, cB.x), eB0b = mul2(rB0.y, cB.y);
            u64 eB1a = mul2(rB1.x, cB.x), eB1b = mul2(rB1.y, cB.y);

            ulonglong2 fv = fp2[dv];
            qA0 = fma2(eA0a, fv.x, qA0); qA0 = fma2(eA0b, fv.y, qA0);
            qA1 = fma2(eA1a, fv.x, qA1); qA1 = fma2(eA1b, fv.y, qA1);
            qB0 = fma2(eB0a, fv.x, qB0); qB0 = fma2(eB0b, fv.y, qB0);
            qB1 = fma2(eB1a, fv.x, qB1); qB1 = fma2(eB1b, fv.y, qB1);

            float fA0[4], fA1[4], fB0[4], fB1[4];
            unpack2(eA0a, fA0[0], fA0[1]); unpack2(eA0b, fA0[2], fA0[3]);
            unpack2(eA1a, fA1[0], fA1[1]); unpack2(eA1b, fA1[2], fA1[3]);
            unpack2(eB0a, fB0[0], fB0[1]); unpack2(eB0b, fB0[2], fB0[3]);
            unpack2(eB1a, fB1[0], fB1[1]); unpack2(eB1b, fB1[2], fB1[3]);

            #pragma unroll
            for (int dd = 0; dd < 4; dd++) {
                int d = dv * 4 + dd;
                ulonglong2 w01 = Wq[d * 2];
                ulonglong2 w23 = Wq[d * 2 + 1];
                u64 sd;
                sd = pk2(fA0[dd], fA0[dd]);
                aA0[0] = fma2(sd, w01.x, aA0[0]); aA0[1] = fma2(sd, w01.y, aA0[1]);
                aA0[2] = fma2(sd, w23.x, aA0[2]); aA0[3] = fma2(sd, w23.y, aA0[3]);
                sd = pk2(fA1[dd], fA1[dd]);
                aA1[0] = fma2(sd, w01.x, aA1[0]); aA1[1] = fma2(sd, w01.y, aA1[1]);
                aA1[2] = fma2(sd, w23.x, aA1[2]); aA1[3] = fma2(sd, w23.y, aA1[3]);
                sd = pk2(fB0[dd], fB0[dd]);
                aB0[0] = fma2(sd, w01.x, aB0[0]); aB0[1] = fma2(sd, w01.y, aB0[1]);
                aB0[2] = fma2(sd, w23.x, aB0[2]); aB0[3] = fma2(sd, w23.y, aB0[3]);
                sd = pk2(fB1[dd], fB1[dd]);
                aB1[0] = fma2(sd, w01.x, aB1[0]); aB1[1] = fma2(sd, w01.y, aB1[1]);
                aB1[2] = fma2(sd, w23.x, aB1[2]); aB1[3] = fma2(sd, w23.y, aB1[3]);
            }
        }

        // --- logits: relu + proj per slot ---
        float gA0 = 0.f, gA1 = 0.f, gB0 = 0.f, gB1 = 0.f;
        #pragma unroll
        for (int k = 0; k < 4; k++) {
            float ha, hb;
            unpack2(aA0[k], ha, hb);
            gA0 += pwb[NA + 2 * k] * fmaxf(ha + pwb[2 * k], 0.f)
                 + pwb[NA + 2 * k + 1] * fmaxf(hb + pwb[2 * k + 1], 0.f);
            unpack2(aA1[k], ha, hb);
            gA1 += pwb[NA + 2 * k] * fmaxf(ha + pwb[2 * k], 0.f)
                 + pwb[NA + 2 * k + 1] * fmaxf(hb + pwb[2 * k + 1], 0.f);
            unpack2(aB0[k], ha, hb);
            gB0 += pwb[NA + 2 * k] * fmaxf(ha + pwb[2 * k], 0.f)
                 + pwb[NA + 2 * k + 1] * fmaxf(hb + pwb[2 * k + 1], 0.f);
            unpack2(aB1[k], ha, hb);
            gB1 += pwb[NA + 2 * k] * fmaxf(ha + pwb[2 * k], 0.f)
                 + pwb[NA + 2 * k + 1] * fmaxf(hb + pwb[2 * k + 1], 0.f);
        }
        float qsA0 = sum2(qA0), qsA1 = sum2(qA1);
        float qsB0 = sum2(qB0), qsB1 = sum2(qB1);

        // --- block max over valid slots ---
        float m = fmaxf(fmaxf(vA0 ? gA0 : -1e30f, vA1 ? gA1 : -1e30f),
                        fmaxf(vB0 ? gB0 : -1e30f, vB1 ? gB1 : -1e30f));
        #pragma unroll
        for (int o = 16; o; o >>= 1) m = fmaxf(m, __shfl_xor_sync(0xffffffffu, m, o));
        if (lane == 0) sredm[wid] = m;
        __syncthreads();
        float gmax = sredm[0];
        #pragma unroll
        for (int k = 1; k < NW; k++) gmax = fmaxf(gmax, sredm[k]);

        float wA0 = vA0 ? __expf(gA0 - gmax) : 0.f;
        float wA1 = vA1 ? __expf(gA1 - gmax) : 0.f;
        float wB0 = vB0 ? __expf(gB0 - gmax) : 0.f;
        float wB1 = vB1 ? __expf(gB1 - gmax) : 0.f;

        // --- block sums of (w, w*q) ---
        float ssum = (wA0 + wA1) + (wB0 + wB1);
        float sq   = (wA0 * qsA0 + wA1 * qsA1) + (wB0 * qsB0 + wB1 * qsB1);
        #pragma unroll
        for (int o = 16; o; o >>= 1) {
            ssum += __shfl_xor_sync(0xffffffffu, ssum, o);
            sq   += __shfl_xor_sync(0xffffffffu, sq,   o);
        }
        if (lane == 0) { sreds[wid] = ssum; sredq[wid] = sq; }
        __syncthreads();

        if (t == 0) {
            float ts = 0.f, tq = 0.f;
            #pragma unroll
            for (int k = 0; k < NW; k++) { ts += sreds[k]; tq += sredq[k]; }
            float z = tq / ts + fcb;
            out[s] = 1.f / (1.f + __expf(-z));
        }
        parity ^= 1;
    }
}

extern "C" void kernel_launch(void* const* d_in, const int* in_sizes, int n_in,
                              void* d_out, int out_size) {
    const float* conts  = (const float*)d_in[0];
    const void*  cates  = d_in[1];
    const float* emb    = (const float*)d_in[3];
    const float* attn_W = (const float*)d_in[4];
    const float* attn_b = (const float*)d_in[5];
    const float* proj_W = (const float*)d_in[6];
    const float* fc_W   = (const float*)d_in[7];
    const float* fc_b   = (const float*)d_in[8];
    float* out = (float*)d_out;

    int batch = in_sizes[0] / CONTF;
    int nblk = batch < NBLK ? batch : NBLK;
    afm_main<<<nblk, TPB>>>(conts, cates, emb, attn_W, attn_b, proj_W,
                            fc_W, fc_b, out, batch);
}

// round 11
// speedup vs baseline: 1.2729x; 1.2729x over previous
#include <cuda_runtime.h>
#include <math.h>
#include <stdint.h>

#define CONTF 13
#define CATEF 26
#define NF    39
#define ED    40
#define NPAIR 741
#define NA    8
#define TPB   384
#define NW    (TPB/32)
#define PAD   44      // 176B row stride: 16B-aligned, conflict-free LDS.128
#define XROWS 39
#define XSZ   (XROWS*PAD)
#define VOCAB 100000
#define NBLK  296     // 2 persistent blocks per SM

typedef unsigned long long u64;

__device__ __forceinline__ u64 mul2(u64 a, u64 b) {
    u64 d; asm("mul.rn.f32x2 %0, %1, %2;" : "=l"(d) : "l"(a), "l"(b)); return d;
}
__device__ __forceinline__ u64 fma2(u64 a, u64 b, u64 c) {
    u64 d; asm("fma.rn.f32x2 %0, %1, %2, %3;" : "=l"(d) : "l"(a), "l"(b), "l"(c)); return d;
}
__device__ __forceinline__ u64 pk2(float lo, float hi) {
    u64 d; asm("mov.b64 %0, {%1, %2};" : "=l"(d) : "f"(lo), "f"(hi)); return d;
}
__device__ __forceinline__ float sum2(u64 v) {
    float lo, hi; asm("mov.b64 {%0, %1}, %2;" : "=f"(lo), "=f"(hi) : "l"(v));
    return lo + hi;
}
__device__ __forceinline__ void cp16(uint32_t dst, const void* src) {
    asm volatile("cp.async.ca.shared.global [%0], [%1], 16;" :: "r"(dst), "l"(src));
}
__device__ __forceinline__ void cp4(uint32_t dst, const void* src) {
    asm volatile("cp.async.ca.shared.global [%0], [%1], 4;" :: "r"(dst), "l"(src));
}

// Decode linear pair index p -> (i, j), i<j, row-major triu(k=1) of 39 fields.
__device__ __forceinline__ void decode_pair(int p, int& i, int& j) {
    float s = sqrtf((float)(5929 - 8 * p));
    int ii = (int)floorf((77.0f - s) * 0.5f);
    while (ii > 0 && ii * (77 - ii) / 2 > p) ii--;
    while ((ii + 1) * (76 - ii) / 2 <= p) ii++;
    i = ii;
    j = p - ii * (77 - ii) / 2 + ii + 1;
}

// ---- constant-bank weights (filled per launch via pack kernel + D2D memcpy) ----
// cWp[dp*8 + a] = (attn_W[a][2dp], attn_W[a][2dp+1]), dp in [0,20)
__constant__ u64   cWp[20 * NA];
__constant__ u64   cFp[20];        // (fc_W[2t], fc_W[2t+1])
__constant__ float cPwb[17];       // attn_b[0:8] | proj_W[0:8] | fc_b

__device__ u64   g_scrW[20 * NA];
__device__ u64   g_scrF[20];
__device__ float g_scrP[17];

__global__ void pack_weights(const float* __restrict__ attn_W,
                             const float* __restrict__ attn_b,
                             const float* __restrict__ proj_W,
                             const float* __restrict__ fc_W,
                             const float* __restrict__ fc_b) {
    int t = threadIdx.x;
    if (t < 160) {
        int dp = t >> 3, a = t & 7;
        g_scrW[t] = pk2(attn_W[a * ED + 2 * dp], attn_W[a * ED + 2 * dp + 1]);
    }
    if (t < 20) g_scrF[t] = pk2(fc_W[2 * t], fc_W[2 * t + 1]);
    if (t < NA) { g_scrP[t] = attn_b[t]; g_scrP[NA + t] = proj_W[t]; }
    if (t == 0) g_scrP[16] = fc_b[0];
}

__global__ __launch_bounds__(TPB, 2) void afm_main(
    const float* __restrict__ conts,
    const void*  __restrict__ cates_raw,
    const float* __restrict__ emb,
    float* __restrict__ out,            // (B, 1)
    int batch)
{
    __shared__ __align__(16) float xs[2][XSZ];        // double-buffered x tiles
    __shared__ float sbase[CONTF * ED];               // emb rows 0..12 (block-lifetime)
    __shared__ float sconts[2][CONTF];
    __shared__ float sredm[NW], sreds[NW], sredq[NW];
    __shared__ int   sflag;

    const int t    = threadIdx.x;
    const int lane = t & 31;
    const int wid  = t >> 5;

    // --- int64-vs-int32 probe: int64 indices < VOCAB -> all hi words 0 ---
    if (wid == 0) {
        const unsigned int* raw = (const unsigned int*)cates_raw;
        unsigned int lo = raw[2 * lane], hi = raw[2 * lane + 1];
        int ok = (hi == 0u && lo < (unsigned)VOCAB);
        unsigned int bal = __ballot_sync(0xffffffffu, ok);
        if (lane == 0) sflag = (bal == 0xffffffffu);
    }

    for (int e = t; e < CONTF * ED; e += TPB) sbase[e] = emb[e];  // rows 0..12
    __syncthreads();

    const int is64 = sflag;
    const long long* c64 = (const long long*)cates_raw;
    const int*       c32 = (const int*)cates_raw;

    const uint32_t xs_a = (uint32_t)__cvta_generic_to_shared(&xs[0][0]);
    const uint32_t sc_a = (uint32_t)__cvta_generic_to_shared(&sconts[0][0]);

    // --- hoisted per-thread pair geometry ---
    const int p0 = t;
    const int p1v = t + TPB;
    const bool v1 = (p1v < NPAIR);
    const int p1 = v1 ? p1v : (NPAIR - 1);
    int i0, j0, i1, j1;
    decode_pair(p0, i0, j0);
    decode_pair(p1, i1, j1);
    const int or0 = i0 * PAD, oc0 = j0 * PAD, or1 = i1 * PAD, oc1 = j1 * PAD;

    // --- prefetch: 26 gathered rows (260 threads x 16B) + 13 conts ---
    #define PREFETCH(b_, buf_) do {                                           \
        if (t < 260) {                                                        \
            int f_ = t / 10, seg_ = t - f_ * 10;                              \
            long long idx_ = is64 ? c64[(long long)(b_) * CATEF + f_]         \
                                  : (long long)c32[(b_) * CATEF + f_];        \
            cp16(xs_a + ((buf_) * XSZ + (CONTF + f_) * PAD + seg_ * 4) * 4,   \
                 emb + idx_ * ED + seg_ * 4);                                 \
        } else if (t < 260 + CONTF) {                                         \
            int r_ = t - 260;                                                 \
            cp4(sc_a + ((buf_) * CONTF + r_) * 4, conts + (b_) * CONTF + r_); \
        }                                                                     \
        asm volatile("cp.async.commit_group;" ::: "memory");                  \
    } while (0)

    const int s0 = blockIdx.x;
    int parity = 0;
    if (s0 < batch) PREFETCH(s0, 0);

    for (int s = s0; s < batch; s += NBLK) {
        float* xb = &xs[parity][0];

        asm volatile("cp.async.wait_group 0;" ::: "memory");
        __syncthreads();

        if (s + NBLK < batch) PREFETCH(s + NBLK, parity ^ 1);

        // continuous-field rows: sbase * conts[s]
        for (int e = t; e < CONTF * ED; e += TPB) {
            int r = e / ED, d = e - r * ED;
            xb[r * PAD + d] = sbase[e] * sconts[parity][r];
        }
        __syncthreads();

        const ulonglong2* xr0 = (const ulonglong2*)(xb + or0);
        const ulonglong2* xc0 = (const ulonglong2*)(xb + oc0);
        const ulonglong2* xr1 = (const ulonglong2*)(xb + or1);
        const ulonglong2* xc1 = (const ulonglong2*)(xb + oc1);

        u64 acc0[NA], acc1[NA];
        #pragma unroll
        for (int a = 0; a < NA; a++) { acc0[a] = 0ull; acc1[a] = 0ull; }
        u64 q0 = 0ull, q1 = 0ull;

        #pragma unroll
        for (int dv = 0; dv < 10; dv++) {          // 4 dims per iter
            ulonglong2 r0 = xr0[dv], c0 = xc0[dv];
            ulonglong2 r1 = xr1[dv], c1 = xc1[dv];
            u64 e0a = mul2(r0.x, c0.x), e0b = mul2(r0.y, c0.y);
            u64 e1a = mul2(r1.x, c1.x), e1b = mul2(r1.y, c1.y);
            #pragma unroll
            for (int k = 0; k < 4; k++) {          // dp = 2*dv, a = 2k,2k+1
                u64 wx = cWp[(2 * dv) * NA + 2 * k];
                u64 wy = cWp[(2 * dv) * NA + 2 * k + 1];
                acc0[2 * k]     = fma2(e0a, wx, acc0[2 * k]);
                acc0[2 * k + 1] = fma2(e0a, wy, acc0[2 * k + 1]);
                acc1[2 * k]     = fma2(e1a, wx, acc1[2 * k]);
                acc1[2 * k + 1] = fma2(e1a, wy, acc1[2 * k + 1]);
            }
            #pragma unroll
            for (int k = 0; k < 4; k++) {          // dp = 2*dv+1
                u64 wx = cWp[(2 * dv + 1) * NA + 2 * k];
                u64 wy = cWp[(2 * dv + 1) * NA + 2 * k + 1];
                acc0[2 * k]     = fma2(e0b, wx, acc0[2 * k]);
                acc0[2 * k + 1] = fma2(e0b, wy, acc0[2 * k + 1]);
                acc1[2 * k]     = fma2(e1b, wx, acc1[2 * k]);
                acc1[2 * k + 1] = fma2(e1b, wy, acc1[2 * k + 1]);
            }
            u64 fva = cFp[2 * dv], fvb = cFp[2 * dv + 1];
            q0 = fma2(e0a, fva, q0); q0 = fma2(e0b, fvb, q0);
            q1 = fma2(e1a, fva, q1); q1 = fma2(e1b, fvb, q1);
        }

        // --- logits: relu + proj ---
        float g0 = 0.f, g1 = 0.f;
        #pragma unroll
        for (int a = 0; a < NA; a++) {
            float h0 = sum2(acc0[a]) + cPwb[a];
            float h1 = sum2(acc1[a]) + cPwb[a];
            g0 += cPwb[NA + a] * fmaxf(h0, 0.f);
            g1 += cPwb[NA + a] * fmaxf(h1, 0.f);
        }
        float qs0 = sum2(q0), qs1 = sum2(q1);

        // --- block max ---
        float m = v1 ? fmaxf(g0, g1) : g0;
        #pragma unroll
        for (int o = 16; o; o >>= 1) m = fmaxf(m, __shfl_xor_sync(0xffffffffu, m, o));
        if (lane == 0) sredm[wid] = m;
        __syncthreads();
        float gmax = sredm[0];
        #pragma unroll
        for (int k = 1; k < NW; k++) gmax = fmaxf(gmax, sredm[k]);

        float w0 = __expf(g0 - gmax);
        float w1 = v1 ? __expf(g1 - gmax) : 0.f;

        // --- block sums of (w, w*q) ---
        float ssum = w0 + w1;
        float sq   = w0 * qs0 + w1 * qs1;
        #pragma unroll
        for (int o = 16; o; o >>= 1) {
            ssum += __shfl_xor_sync(0xffffffffu, ssum, o);
            sq   += __shfl_xor_sync(0xffffffffu, sq,   o);
        }
        if (lane == 0) { sreds[wid] = ssum; sredq[wid] = sq; }
        __syncthreads();

        if (t == 0) {
            float ts = 0.f, tq = 0.f;
            #pragma unroll
            for (int k = 0; k < NW; k++) { ts += sreds[k]; tq += sredq[k]; }
            float z = tq / ts + cPwb[16];
            out[s] = 1.f / (1.f + __expf(-z));
        }
        parity ^= 1;
    }
}

extern "C" void kernel_launch(void* const* d_in, const int* in_sizes, int n_in,
                              void* d_out, int out_size) {
    const float* conts  = (const float*)d_in[0];
    const void*  cates  = d_in[1];
    const float* emb    = (const float*)d_in[3];
    const float* attn_W = (const float*)d_in[4];
    const float* attn_b = (const float*)d_in[5];
    const float* proj_W = (const float*)d_in[6];
    const float* fc_W   = (const float*)d_in[7];
    const float* fc_b   = (const float*)d_in[8];
    float* out = (float*)d_out;

    int batch = in_sizes[0] / CONTF;

    // pack weights into f32x2 layout, then D2D-copy into the constant bank
    pack_weights<<<1, 192>>>(attn_W, attn_b, proj_W, fc_W, fc_b);
    void *pW = nullptr, *pF = nullptr, *pP = nullptr;
    cudaGetSymbolAddress(&pW, g_scrW);
    cudaGetSymbolAddress(&pF, g_scrF);
    cudaGetSymbolAddress(&pP, g_scrP);
    cudaMemcpyToSymbolAsync(cWp, pW, sizeof(g_scrW), 0, cudaMemcpyDeviceToDevice, 0);
    cudaMemcpyToSymbolAsync(cFp, pF, sizeof(g_scrF), 0, cudaMemcpyDeviceToDevice, 0);
    cudaMemcpyToSymbolAsync(cPwb, pP, sizeof(g_scrP), 0, cudaMemcpyDeviceToDevice, 0);

    int nblk = batch < NBLK ? batch : NBLK;
    afm_main<<<nblk, TPB>>>(conts, cates, emb, out, batch);
}